// round 5
// baseline (speedup 1.0000x reference)
#include <cuda_runtime.h>

#define BSZ 8
#define SEQ 2048
#define DIM 512
#define HID 1024
#define M_TOT (BSZ * SEQ)   /* 16384 */
#define K_TOT (3 * DIM)     /* 1536  */

#define BM 128
#define BN 128
#define BK 16

// ---------------- scratch (no allocations allowed) ----------------
__device__ float g_wt[(size_t)K_TOT * HID];        // 6 MB:  wt[kc][o], kc = k*512+d
__device__ float g_h[(size_t)M_TOT * HID];         // 64 MB: post-ReLU conv activations
__device__ int   g_flag[M_TOT];                    // argmax result per (b,n)
__device__ int   g_groups[BSZ * SEQ];              // compacted boundary list per batch

// ---------------- 0: transpose conv_w (H,D,3) -> wt[k*D+d][o] ----------------
__global__ void wt_transpose_kernel(const float* __restrict__ conv_w) {
    int idx = blockIdx.x * 256 + threadIdx.x;
    if (idx >= K_TOT * HID) return;
    int o  = idx % HID;
    int kc = idx / HID;
    int k  = kc / DIM;
    int d  = kc % DIM;
    g_wt[idx] = conv_w[(size_t)o * (DIM * 3) + d * 3 + k];
}

// ---------------- 1: implicit-im2col SGEMM + bias + ReLU ----------------
// h[m, o] = sum_{k,d} x[b, n+k-1, d] * w[o, d, k]   (zero-pad at batch edges)
// A[m][kc] with kc = k*512 + d;  BK=16 chunks never straddle a k boundary.
// Double-buffered smem with register prefetch: one __syncthreads per K-iter,
// next tile's global loads issued before the compute loop (latency hidden).
__global__ __launch_bounds__(256) void conv_gemm_kernel(const float* __restrict__ x,
                                                        const float* __restrict__ conv_b) {
    __shared__ float As[2][BK][BM];
    __shared__ float Bs[2][BK][BN];
    const int tid  = threadIdx.x;
    const int row0 = blockIdx.y * BM;
    const int col0 = blockIdx.x * BN;
    const int tx   = tid & 15;
    const int ty   = tid >> 4;

    // per-thread staging indices (loop-invariant)
    const int a_ml0 = tid >> 2,         a_q0 = tid & 3;
    const int a_ml1 = (tid + 256) >> 2, a_q1 = (tid + 256) & 3;
    const int b_kl0 = tid >> 5,         b_o0 = tid & 31;
    const int b_kl1 = (tid + 256) >> 5, b_o1 = (tid + 256) & 31;

    float acc[8][8];
#pragma unroll
    for (int i = 0; i < 8; i++)
#pragma unroll
        for (int j = 0; j < 8; j++) acc[i][j] = 0.f;

    float4 ra[2], rb[2];

    // ---- tile fetch into registers (im2col for A, plain for B) ----
    auto fetch = [&](int kk) {
        const int k     = kk >> 9;          // tap index 0..2
        const int dbase = kk & (DIM - 1);
#pragma unroll
        for (int i = 0; i < 2; i++) {
            int ml = i ? a_ml1 : a_ml0;
            int q  = i ? a_q1  : a_q0;
            int m  = row0 + ml;
            int n  = m & (SEQ - 1);
            int b  = m >> 11;
            int r  = n + k - 1;             // shifted source row within batch
            float4 v = make_float4(0.f, 0.f, 0.f, 0.f);
            if ((unsigned)r < SEQ)
                v = *reinterpret_cast<const float4*>(
                        x + ((size_t)(b * SEQ + r) * DIM + dbase + q * 4));
            ra[i] = v;
        }
#pragma unroll
        for (int i = 0; i < 2; i++) {
            int kl = i ? b_kl1 : b_kl0;
            int o4 = i ? b_o1  : b_o0;
            rb[i] = *reinterpret_cast<const float4*>(
                        g_wt + (size_t)(kk + kl) * HID + col0 + o4 * 4);
        }
    };
    auto stage = [&](int buf) {
#pragma unroll
        for (int i = 0; i < 2; i++) {
            int ml = i ? a_ml1 : a_ml0;
            int q  = i ? a_q1  : a_q0;
            As[buf][q * 4 + 0][ml] = ra[i].x;
            As[buf][q * 4 + 1][ml] = ra[i].y;
            As[buf][q * 4 + 2][ml] = ra[i].z;
            As[buf][q * 4 + 3][ml] = ra[i].w;
            int kl = i ? b_kl1 : b_kl0;
            int o4 = i ? b_o1  : b_o0;
            *reinterpret_cast<float4*>(&Bs[buf][kl][o4 * 4]) = rb[i];
        }
    };

    fetch(0);
    stage(0);
    __syncthreads();

    int buf = 0;
    for (int kk = 0; kk < K_TOT; kk += BK) {
        const int nxt = kk + BK;
        if (nxt < K_TOT) fetch(nxt);        // LDGs in flight during compute

#pragma unroll
        for (int kl = 0; kl < BK; kl++) {
            float a[8], bb[8];
            *reinterpret_cast<float4*>(a)      = *reinterpret_cast<float4*>(&As[buf][kl][ty * 8]);
            *reinterpret_cast<float4*>(a + 4)  = *reinterpret_cast<float4*>(&As[buf][kl][ty * 8 + 4]);
            *reinterpret_cast<float4*>(bb)     = *reinterpret_cast<float4*>(&Bs[buf][kl][tx * 8]);
            *reinterpret_cast<float4*>(bb + 4) = *reinterpret_cast<float4*>(&Bs[buf][kl][tx * 8 + 4]);
#pragma unroll
            for (int i = 0; i < 8; i++)
#pragma unroll
                for (int j = 0; j < 8; j++) acc[i][j] += a[i] * bb[j];
        }

        if (nxt < K_TOT) stage(buf ^ 1);    // write alternate buffer (no reader conflict)
        __syncthreads();
        buf ^= 1;
    }

    // epilogue: bias + ReLU, write h
#pragma unroll
    for (int i = 0; i < 8; i++) {
        int m = row0 + ty * 8 + i;
        float* hp = g_h + (size_t)m * HID + col0 + tx * 8;
#pragma unroll
        for (int j = 0; j < 8; j += 4) {
            int ob = col0 + tx * 8 + j;
            float4 v;
            v.x = fmaxf(acc[i][j + 0] + conv_b[ob + 0], 0.f);
            v.y = fmaxf(acc[i][j + 1] + conv_b[ob + 1], 0.f);
            v.z = fmaxf(acc[i][j + 2] + conv_b[ob + 2], 0.f);
            v.w = fmaxf(acc[i][j + 3] + conv_b[ob + 3], 0.f);
            *reinterpret_cast<float4*>(hp + j) = v;
        }
    }
}

// ---------------- 2: LayerNorm + 2-col projection + argmax ----------------
__device__ __forceinline__ float block_reduce(float val, float* red, int t) {
#pragma unroll
    for (int off = 16; off; off >>= 1)
        val += __shfl_down_sync(0xffffffffu, val, off);
    int lane = t & 31, w = t >> 5;
    __syncthreads();                 // protect shared slot reuse across calls
    if (lane == 0) red[w] = val;
    __syncthreads();
    float r = 0.f;
#pragma unroll
    for (int i = 0; i < 8; i++) r += red[i];
    return r;                        // broadcast to all threads
}

__global__ __launch_bounds__(256) void ln_proj_kernel(const float* __restrict__ ln_g,
                                                      const float* __restrict__ ln_b,
                                                      const float* __restrict__ proj_w,
                                                      const float* __restrict__ proj_b,
                                                      float* __restrict__ out_probs) {
    const int m = blockIdx.x;
    const int t = threadIdx.x;
    const float* hrow = g_h + (size_t)m * HID;
    __shared__ float red[8];

    float v[4];
    float s = 0.f;
#pragma unroll
    for (int j = 0; j < 4; j++) { v[j] = hrow[t + j * 256]; s += v[j]; }

    float mu = block_reduce(s, red, t) * (1.f / HID);
    float sq = 0.f;
#pragma unroll
    for (int j = 0; j < 4; j++) { float d = v[j] - mu; sq += d * d; }
    float var = block_reduce(sq, red, t) * (1.f / HID);
    float rs  = rsqrtf(var + 1e-5f);

    float p0 = 0.f, p1 = 0.f;
#pragma unroll
    for (int j = 0; j < 4; j++) {
        int o = t + j * 256;
        float y = (v[j] - mu) * rs * ln_g[o] + ln_b[o];
        float2 w2 = *reinterpret_cast<const float2*>(proj_w + 2 * o);
        p0 += y * w2.x;
        p1 += y * w2.y;
    }
    p0 = block_reduce(p0, red, t);
    p1 = block_reduce(p1, red, t);
    if (t == 0) {
        p0 += proj_b[0];
        p1 += proj_b[1];
        out_probs[2 * m]     = p0;
        out_probs[2 * m + 1] = p1;
        g_flag[m] = (p1 > p0) ? 1 : 0;   // argmax: index 1 only if strictly greater
    }
}

// ---------------- 3: stable compaction of boundary positions ----------------
// kept(n): n==N-1 always; n==0 never; else g==0.  value = n+1; zeros padded.
__global__ __launch_bounds__(1024) void compact_kernel() {
    const int b = blockIdx.x;
    const int t = threadIdx.x;
    __shared__ int buf[2][1024];

    const int n0 = 2 * t, n1 = 2 * t + 1;
    int k0 = (n0 == 0) ? 0 : ((n0 == SEQ - 1) ? 1 : (g_flag[b * SEQ + n0] == 0));
    int k1 = (n1 == SEQ - 1) ? 1 : (g_flag[b * SEQ + n1] == 0);
    int pairsum = k0 + k1;

    int src = 0;
    buf[0][t] = pairsum;
    __syncthreads();
    int incl = pairsum;
    for (int off = 1; off < 1024; off <<= 1) {
        incl = buf[src][t];
        if (t >= off) incl += buf[src][t - off];
        buf[1 - src][t] = incl;
        src ^= 1;
        __syncthreads();
    }
    int excl = incl - pairsum;

    g_groups[b * SEQ + n0] = 0;
    g_groups[b * SEQ + n1] = 0;
    __syncthreads();
    if (k0) g_groups[b * SEQ + excl]      = n0 + 1;
    if (k1) g_groups[b * SEQ + excl + k0] = n1 + 1;
}

// ---------------- 4: grouping matrix (interval indicator) ----------------
// row i, col t-1 (t=1..N): 1 iff G_{i-1} < t <= G_i   (G_{-1} := 0)
__global__ __launch_bounds__(256) void grouping_kernel(float* __restrict__ out) {
    unsigned e = blockIdx.x * 256u + threadIdx.x;     // 8*2048*512 = 2^23 float4 slots
    int c = e & 511;
    int i = (e >> 9) & (SEQ - 1);
    int b = e >> 20;
    int Gi = g_groups[b * SEQ + i];
    int Gp = (i > 0) ? g_groups[b * SEQ + i - 1] : 0;
    int t0 = 4 * c + 1;
    float4 v;
    v.x = (t0     > Gp && t0     <= Gi) ? 1.f : 0.f;
    v.y = (t0 + 1 > Gp && t0 + 1 <= Gi) ? 1.f : 0.f;
    v.z = (t0 + 2 > Gp && t0 + 2 <= Gi) ? 1.f : 0.f;
    v.w = (t0 + 3 > Gp && t0 + 3 <= Gi) ? 1.f : 0.f;
    *reinterpret_cast<float4*>(out + ((size_t)(b * SEQ + i) * SEQ + 4 * c)) = v;
}

// ---------------- launch ----------------
extern "C" void kernel_launch(void* const* d_in, const int* in_sizes, int n_in,
                              void* d_out, int out_size) {
    const float* x      = (const float*)d_in[0];
    const float* conv_w = (const float*)d_in[1];
    const float* conv_b = (const float*)d_in[2];
    const float* ln_g   = (const float*)d_in[3];
    const float* ln_b   = (const float*)d_in[4];
    const float* proj_w = (const float*)d_in[5];
    const float* proj_b = (const float*)d_in[6];

    float* out       = (float*)d_out;
    float* out_probs = out;                          // (B,N,2) = 32768 floats
    float* out_mat   = out + (size_t)M_TOT * 2;      // (B,N,N)

    wt_transpose_kernel<<<(K_TOT * HID + 255) / 256, 256>>>(conv_w);

    dim3 gg(HID / BN, M_TOT / BM);
    conv_gemm_kernel<<<gg, 256>>>(x, conv_b);

    ln_proj_kernel<<<M_TOT, 256>>>(ln_g, ln_b, proj_w, proj_b, out_probs);

    compact_kernel<<<BSZ, 1024>>>();

    grouping_kernel<<<(BSZ * SEQ * (SEQ / 4)) / 256, 256>>>(out_mat);
}

// round 11
// speedup vs baseline: 1.2071x; 1.2071x over previous
#include <cuda_runtime.h>
#include <cstdint>

#define BSZ 8
#define SEQ 2048
#define DIM 512
#define HID 1024
#define M_TOT (BSZ * SEQ)   /* 16384 */
#define K_TOT (3 * DIM)     /* 1536  */

#define CHUNKS 96           /* K_TOT / 16 */
#define NBLK   8            /* HID / 128  */
#define MBLK   128          /* M_TOT / 128 */

// ---------------- scratch (no allocations allowed) ----------------
// A fragments: per (m-block, chunk): 4096 floats = [hi 2048 | lo 2048],
//   hi: [s(2)][t(8)][lane(32)][reg(4)]  (16B per lane -> LDS.128)
__device__ float g_af[(size_t)MBLK * CHUNKS * 4096];   // 201 MB
// B fragments: per (n-block, chunk): 4096 floats = [hi 2048 | lo 2048],
//   hi: [s(2)][u(16)][lane(32)][reg(2)] (8B per lane -> LDS.64)
__device__ float g_bf[(size_t)NBLK * CHUNKS * 4096];   // 12.6 MB
__device__ float g_h[(size_t)M_TOT * HID];             // 64 MB post-ReLU activations
__device__ int   g_flag[M_TOT];
__device__ int   g_groups[BSZ * SEQ];

// ---------------- helpers ----------------
__device__ __forceinline__ uint32_t smem_u32(const void* p) {
    uint32_t a;
    asm("{ .reg .u64 t; cvta.to.shared.u64 t, %1; cvt.u32.u64 %0, t; }" : "=r"(a) : "l"(p));
    return a;
}
__device__ __forceinline__ float tf32_hi(float v) {
    uint32_t h;
    asm("cvt.rna.tf32.f32 %0, %1;" : "=r"(h) : "f"(v));
    return __uint_as_float(h);
}
__device__ __forceinline__ void cp16(uint32_t s, const void* g) {
    asm volatile("cp.async.cg.shared.global [%0], [%1], 16;" :: "r"(s), "l"(g) : "memory");
}
__device__ __forceinline__ void lds128(uint32_t* r, uint32_t a) {
    asm volatile("ld.shared.v4.b32 {%0,%1,%2,%3}, [%4];"
                 : "=r"(r[0]), "=r"(r[1]), "=r"(r[2]), "=r"(r[3]) : "r"(a));
}
__device__ __forceinline__ void lds64(uint32_t* r, uint32_t a) {
    asm volatile("ld.shared.v2.b32 {%0,%1}, [%2];" : "=r"(r[0]), "=r"(r[1]) : "r"(a));
}
__device__ __forceinline__ void mma8(float* c, const uint32_t* a, const uint32_t* b) {
    asm volatile(
        "mma.sync.aligned.m16n8k8.row.col.f32.tf32.tf32.f32 "
        "{%0,%1,%2,%3}, {%4,%5,%6,%7}, {%8,%9}, {%0,%1,%2,%3};"
        : "+f"(c[0]), "+f"(c[1]), "+f"(c[2]), "+f"(c[3])
        : "r"(a[0]), "r"(a[1]), "r"(a[2]), "r"(a[3]), "r"(b[0]), "r"(b[1]));
}

// ---------------- 0a: B fragments (weights, hi/lo split) ----------------
// C[m][o] = sum_k A[m][k]*W[o][k]; B fragment b0=(k%8 in 0..3, col=o%8), b1=(k%8+4).
__global__ void bfrag_kernel(const float* __restrict__ conv_w) {
    int id = blockIdx.x * 256 + threadIdx.x;
    if (id >= HID * K_TOT) return;
    int o = id / K_TOT, k = id - o * K_TOT;
    int tap = k >> 9, d = k & 511;
    float v = conv_w[((size_t)o * DIM + d) * 3 + tap];
    float h = tf32_hi(v);
    int nb = o >> 7, ch = k >> 4, s = (k >> 3) & 1, u = (o >> 3) & 15;
    int lane = (o & 7) * 4 + (k & 3);
    int reg  = (k >> 2) & 1;
    size_t base = (size_t)(nb * CHUNKS + ch) * 4096 + ((s * 16 + u) * 32 + lane) * 2 + reg;
    g_bf[base]        = h;
    g_bf[base + 2048] = v - h;
}

// ---------------- 0b: A fragments (im2col + hi/lo split, fragment-ordered) ----------------
// thread -> one (mb, ch, s, t, lane); gathers a0..a3 = x(r,c),(r+8,c),(r,c+4),(r+8,c+4)
__global__ __launch_bounds__(256) void afrag_kernel(const float* __restrict__ x) {
    int id   = blockIdx.x * 256 + threadIdx.x;      // exactly 6,291,456 total
    int lane = id & 31;
    int t    = (id >> 5) & 7;
    int s    = (id >> 8) & 1;
    int rest = id >> 9;                              // mb*96 + ch
    int ch   = rest % CHUNKS;
    int mb   = rest / CHUNKS;
    int r = lane >> 2, cc = lane & 3;
    int m0 = mb * 128 + t * 16 + r;                  // m0 and m0+8 share the batch (16 | 2048)
    int k0 = ch * 16 + s * 8 + cc;                   // k0, k0+4 share the tap (8-block within 512)
    int tap = k0 >> 9, d = k0 & 511;
    int b  = m0 >> 11, n = m0 & (SEQ - 1);
    int ra = n + tap - 1, rb = ra + 8;
    float v00 = 0.f, v10 = 0.f, v01 = 0.f, v11 = 0.f;
    if ((unsigned)ra < SEQ) {
        const float* p = x + ((size_t)(b * SEQ + ra) * DIM + d);
        v00 = p[0]; v01 = p[4];
    }
    if ((unsigned)rb < SEQ) {
        const float* p = x + ((size_t)(b * SEQ + rb) * DIM + d);
        v10 = p[0]; v11 = p[4];
    }
    float h0 = tf32_hi(v00), h1 = tf32_hi(v10), h2 = tf32_hi(v01), h3 = tf32_hi(v11);
    size_t base = (size_t)rest * 4096 + ((s * 8 + t) * 32 + lane) * 4;
    *reinterpret_cast<float4*>(g_af + base)        = make_float4(h0, h1, h2, h3);
    *reinterpret_cast<float4*>(g_af + base + 2048) =
        make_float4(v00 - h0, v10 - h1, v01 - h2, v11 - h3);
}

// ---------------- 1: conv GEMM via mma.sync tf32 x3 + bias + ReLU ----------------
// 256 thr = 8 warps (warpM 2 x warpN 4), warp tile 64x32; 3-stage cp.async pipeline.
__global__ __launch_bounds__(256) void conv_mma_kernel(const float* __restrict__ conv_b) {
    extern __shared__ float smem[];
    const uint32_t sb = smem_u32(smem);
    const int tid  = threadIdx.x;
    const int wid  = tid >> 5, lane = tid & 31;
    const int warpM = wid & 1, warpN = wid >> 1;
    const int mb = blockIdx.y, nb = blockIdx.x;
    const float* Ag = g_af + (size_t)mb * CHUNKS * 4096;
    const float* Bg = g_bf + (size_t)nb * CHUNKS * 4096;

    float acc[4][4][4];
#pragma unroll
    for (int i = 0; i < 4; i++)
#pragma unroll
        for (int j = 0; j < 4; j++)
#pragma unroll
            for (int q = 0; q < 4; q++) acc[i][j][q] = 0.f;

    auto issue = [&](int c) {
        uint32_t sA = sb + (uint32_t)(c % 3) * 32768u;
        const float* ga = Ag + (size_t)c * 4096;
        const float* gb = Bg + (size_t)c * 4096;
#pragma unroll
        for (int i = 0; i < 4; i++) cp16(sA + (i * 256 + tid) * 16, ga + (i * 256 + tid) * 4);
#pragma unroll
        for (int i = 0; i < 4; i++) cp16(sA + 16384 + (i * 256 + tid) * 16, gb + (i * 256 + tid) * 4);
        asm volatile("cp.async.commit_group;" ::: "memory");
    };

    issue(0);
    issue(1);

    for (int c = 0; c < CHUNKS; c++) {
        if (c < CHUNKS - 1)
            asm volatile("cp.async.wait_group 1;" ::: "memory");
        else
            asm volatile("cp.async.wait_group 0;" ::: "memory");
        __syncthreads();                 // chunk c visible; all warps done with c-1
        if (c + 2 < CHUNKS) issue(c + 2);   // stage (c+2)%3 == (c-1)%3, freed by the sync

        uint32_t Ab = sb + (uint32_t)(c % 3) * 32768u;
        uint32_t Bb = Ab + 16384;
#pragma unroll
        for (int s = 0; s < 2; s++) {
            uint32_t ah[4][4], al[4][4], bh[4][2], bl[4][2];
#pragma unroll
            for (int tt = 0; tt < 4; tt++) {
                uint32_t a = Ab + (((s * 8 + warpM * 4 + tt) * 32 + lane) << 4);
                lds128(ah[tt], a);
                lds128(al[tt], a + 8192);
            }
#pragma unroll
            for (int uu = 0; uu < 4; uu++) {
                uint32_t a = Bb + (((s * 16 + warpN * 4 + uu) * 32 + lane) << 3);
                lds64(bh[uu], a);
                lds64(bl[uu], a + 8192);
            }
#pragma unroll
            for (int tt = 0; tt < 4; tt++)
#pragma unroll
                for (int uu = 0; uu < 4; uu++) {
                    mma8(acc[tt][uu], ah[tt], bh[uu]);   // hi*hi
                    mma8(acc[tt][uu], ah[tt], bl[uu]);   // hi*lo
                    mma8(acc[tt][uu], al[tt], bh[uu]);   // lo*hi
                }
        }
    }

    // epilogue: bias + ReLU -> g_h.  c-frag: c0=(r,2c), c1=(r,2c+1), c2=(r+8,2c), c3=(r+8,2c+1)
    const int row0 = mb * 128, col0 = nb * 128;
#pragma unroll
    for (int tt = 0; tt < 4; tt++) {
        int m0 = row0 + warpM * 64 + tt * 16 + (lane >> 2);
#pragma unroll
        for (int uu = 0; uu < 4; uu++) {
            int o0 = col0 + warpN * 32 + uu * 8 + 2 * (lane & 3);
            float2 bias = *reinterpret_cast<const float2*>(conv_b + o0);
            float2 v0, v1;
            v0.x = fmaxf(acc[tt][uu][0] + bias.x, 0.f);
            v0.y = fmaxf(acc[tt][uu][1] + bias.y, 0.f);
            v1.x = fmaxf(acc[tt][uu][2] + bias.x, 0.f);
            v1.y = fmaxf(acc[tt][uu][3] + bias.y, 0.f);
            *reinterpret_cast<float2*>(g_h + (size_t)m0 * HID + o0)       = v0;
            *reinterpret_cast<float2*>(g_h + (size_t)(m0 + 8) * HID + o0) = v1;
        }
    }
}

// ---------------- 2: LayerNorm + 2-col projection + argmax ----------------
__device__ __forceinline__ float block_reduce(float val, float* red, int t) {
#pragma unroll
    for (int off = 16; off; off >>= 1)
        val += __shfl_down_sync(0xffffffffu, val, off);
    int lane = t & 31, w = t >> 5;
    __syncthreads();
    if (lane == 0) red[w] = val;
    __syncthreads();
    float r = 0.f;
#pragma unroll
    for (int i = 0; i < 8; i++) r += red[i];
    return r;
}

__global__ __launch_bounds__(256) void ln_proj_kernel(const float* __restrict__ ln_g,
                                                      const float* __restrict__ ln_b,
                                                      const float* __restrict__ proj_w,
                                                      const float* __restrict__ proj_b,
                                                      float* __restrict__ out_probs) {
    const int m = blockIdx.x;
    const int t = threadIdx.x;
    const float* hrow = g_h + (size_t)m * HID;
    __shared__ float red[8];

    float v[4];
    float s = 0.f;
#pragma unroll
    for (int j = 0; j < 4; j++) { v[j] = hrow[t + j * 256]; s += v[j]; }

    float mu = block_reduce(s, red, t) * (1.f / HID);
    float sq = 0.f;
#pragma unroll
    for (int j = 0; j < 4; j++) { float d = v[j] - mu; sq += d * d; }
    float var = block_reduce(sq, red, t) * (1.f / HID);
    float rs  = rsqrtf(var + 1e-5f);

    float p0 = 0.f, p1 = 0.f;
#pragma unroll
    for (int j = 0; j < 4; j++) {
        int o = t + j * 256;
        float y = (v[j] - mu) * rs * ln_g[o] + ln_b[o];
        float2 w2 = *reinterpret_cast<const float2*>(proj_w + 2 * o);
        p0 += y * w2.x;
        p1 += y * w2.y;
    }
    p0 = block_reduce(p0, red, t);
    p1 = block_reduce(p1, red, t);
    if (t == 0) {
        p0 += proj_b[0];
        p1 += proj_b[1];
        out_probs[2 * m]     = p0;
        out_probs[2 * m + 1] = p1;
        g_flag[m] = (p1 > p0) ? 1 : 0;   // argmax: index 1 only if strictly greater
    }
}

// ---------------- 3: stable compaction of boundary positions ----------------
__global__ __launch_bounds__(1024) void compact_kernel() {
    const int b = blockIdx.x;
    const int t = threadIdx.x;
    __shared__ int buf[2][1024];

    const int n0 = 2 * t, n1 = 2 * t + 1;
    int k0 = (n0 == 0) ? 0 : ((n0 == SEQ - 1) ? 1 : (g_flag[b * SEQ + n0] == 0));
    int k1 = (n1 == SEQ - 1) ? 1 : (g_flag[b * SEQ + n1] == 0);
    int pairsum = k0 + k1;

    int src = 0;
    buf[0][t] = pairsum;
    __syncthreads();
    int incl = pairsum;
    for (int off = 1; off < 1024; off <<= 1) {
        incl = buf[src][t];
        if (t >= off) incl += buf[src][t - off];
        buf[1 - src][t] = incl;
        src ^= 1;
        __syncthreads();
    }
    int excl = incl - pairsum;

    g_groups[b * SEQ + n0] = 0;
    g_groups[b * SEQ + n1] = 0;
    __syncthreads();
    if (k0) g_groups[b * SEQ + excl]      = n0 + 1;
    if (k1) g_groups[b * SEQ + excl + k0] = n1 + 1;
}

// ---------------- 4: grouping matrix (interval indicator) ----------------
__global__ __launch_bounds__(256) void grouping_kernel(float* __restrict__ out) {
    unsigned e = blockIdx.x * 256u + threadIdx.x;
    int c = e & 511;
    int i = (e >> 9) & (SEQ - 1);
    int b = e >> 20;
    int Gi = g_groups[b * SEQ + i];
    int Gp = (i > 0) ? g_groups[b * SEQ + i - 1] : 0;
    int t0 = 4 * c + 1;
    float4 v;
    v.x = (t0     > Gp && t0     <= Gi) ? 1.f : 0.f;
    v.y = (t0 + 1 > Gp && t0 + 1 <= Gi) ? 1.f : 0.f;
    v.z = (t0 + 2 > Gp && t0 + 2 <= Gi) ? 1.f : 0.f;
    v.w = (t0 + 3 > Gp && t0 + 3 <= Gi) ? 1.f : 0.f;
    *reinterpret_cast<float4*>(out + ((size_t)(b * SEQ + i) * SEQ + 4 * c)) = v;
}

// ---------------- launch ----------------
extern "C" void kernel_launch(void* const* d_in, const int* in_sizes, int n_in,
                              void* d_out, int out_size) {
    const float* x      = (const float*)d_in[0];
    const float* conv_w = (const float*)d_in[1];
    const float* conv_b = (const float*)d_in[2];
    const float* ln_g   = (const float*)d_in[3];
    const float* ln_b   = (const float*)d_in[4];
    const float* proj_w = (const float*)d_in[5];
    const float* proj_b = (const float*)d_in[6];

    float* out       = (float*)d_out;
    float* out_probs = out;                          // (B,N,2)
    float* out_mat   = out + (size_t)M_TOT * 2;      // (B,N,N)

    bfrag_kernel<<<(HID * K_TOT + 255) / 256, 256>>>(conv_w);
    afrag_kernel<<<24576, 256>>>(x);

    cudaFuncSetAttribute(conv_mma_kernel, cudaFuncAttributeMaxDynamicSharedMemorySize, 3 * 32768);
    conv_mma_kernel<<<dim3(NBLK, MBLK), 256, 3 * 32768>>>(conv_b);

    ln_proj_kernel<<<M_TOT, 256>>>(ln_g, ln_b, proj_w, proj_b, out_probs);

    compact_kernel<<<BSZ, 1024>>>();

    grouping_kernel<<<(BSZ * SEQ * (SEQ / 4)) / 256, 256>>>(out_mat);
}

// round 12
// speedup vs baseline: 3.2984x; 2.7326x over previous
#include <cuda_runtime.h>
#include <cuda_fp16.h>
#include <cstdint>

#define BSZ 8
#define SEQ 2048
#define DIM 512
#define HID 1024
#define M_TOT (BSZ * SEQ)   /* 16384 */
#define K_TOT (3 * DIM)     /* 1536  */

#define CHUNKS 96           /* K_TOT / 16 */
#define NBLK   8            /* HID / 128  */
#define MBLK   128          /* M_TOT / 128 */

// ---------------- scratch (no allocations allowed) ----------------
// A fragments (fp16 hi/lo split), per (m-block, chunk): 2048 u32 = [hi 1024 | lo 1024]
//   hi: [t(8)][lane(32)][reg(4)]  (16B per lane -> LDS.128); 100 MB total
__device__ uint32_t g_af[(size_t)MBLK * CHUNKS * 2048];
// B fragments, per (n-block, chunk): 2048 u32 = [hi 1024 | lo 1024]
//   hi: [u(16)][lane(32)][reg(2)] (8B per lane -> LDS.64); 6.3 MB total
__device__ uint32_t g_bf[(size_t)NBLK * CHUNKS * 2048];
__device__ float g_h[(size_t)M_TOT * HID];             // 64 MB post-ReLU activations
__device__ int   g_flag[M_TOT];
__device__ int   g_groups[BSZ * SEQ];

// ---------------- helpers ----------------
__device__ __forceinline__ uint32_t smem_u32(const void* p) {
    uint32_t a;
    asm("{ .reg .u64 t; cvta.to.shared.u64 t, %1; cvt.u32.u64 %0, t; }" : "=r"(a) : "l"(p));
    return a;
}
// fp16 two-way split: v = hi + lo (hi 11 bits, lo next 11 bits)
__device__ __forceinline__ void split2(float a, float b, uint32_t& hi, uint32_t& lo) {
    __half ha = __float2half_rn(a), hb = __float2half_rn(b);
    __half la = __float2half_rn(a - __half2float(ha));
    __half lb = __float2half_rn(b - __half2float(hb));
    __half2 h2 = __halves2half2(ha, hb), l2 = __halves2half2(la, lb);
    hi = *reinterpret_cast<uint32_t*>(&h2);
    lo = *reinterpret_cast<uint32_t*>(&l2);
}
__device__ __forceinline__ void cp16(uint32_t s, const void* g) {
    asm volatile("cp.async.cg.shared.global [%0], [%1], 16;" :: "r"(s), "l"(g) : "memory");
}
__device__ __forceinline__ void lds128(uint32_t* r, uint32_t a) {
    asm volatile("ld.shared.v4.b32 {%0,%1,%2,%3}, [%4];"
                 : "=r"(r[0]), "=r"(r[1]), "=r"(r[2]), "=r"(r[3]) : "r"(a));
}
__device__ __forceinline__ void lds64(uint32_t* r, uint32_t a) {
    asm volatile("ld.shared.v2.b32 {%0,%1}, [%2];" : "=r"(r[0]), "=r"(r[1]) : "r"(a));
}
__device__ __forceinline__ void mma16(float* c, const uint32_t* a, const uint32_t* b) {
    asm volatile(
        "mma.sync.aligned.m16n8k16.row.col.f32.f16.f16.f32 "
        "{%0,%1,%2,%3}, {%4,%5,%6,%7}, {%8,%9}, {%0,%1,%2,%3};"
        : "+f"(c[0]), "+f"(c[1]), "+f"(c[2]), "+f"(c[3])
        : "r"(a[0]), "r"(a[1]), "r"(a[2]), "r"(a[3]), "r"(b[0]), "r"(b[1]));
}

// ---------------- 0a: B fragments (weights, fp16 hi/lo) ----------------
// m16n8k16 B-frag (col-major KxN): b0 = {B(2c,n),B(2c+1,n)}, b1 = {B(2c+8,n),B(2c+9,n)},
// n = lane>>2, c = lane&3.  B(k,o) = conv_w[o][d(k)*3 + tap(k)].
__global__ void bfrag_kernel(const float* __restrict__ conv_w) {
    int id   = blockIdx.x * 256 + threadIdx.x;   // 8*96*16*32 = 393216 exactly
    int lane = id & 31;
    int u    = (id >> 5) & 15;
    int rest = id >> 9;                          // nb*96 + ch
    int ch   = rest % CHUNKS;
    int nb   = rest / CHUNKS;
    int o  = nb * 128 + u * 8 + (lane >> 2);
    int k0 = ch * 16 + (lane & 3) * 2;
    int tap = k0 >> 9, d = k0 & 511;
    const float* wp = conv_w + (size_t)o * K_TOT + tap;   // [o][d*3+tap]
    float w0 = wp[(d    ) * 3], w1 = wp[(d + 1) * 3];
    float w2 = wp[(d + 8) * 3], w3 = wp[(d + 9) * 3];
    uint32_t h0, l0, h1, l1;
    split2(w0, w1, h0, l0);
    split2(w2, w3, h1, l1);
    size_t base = (size_t)rest * 2048 + (u * 32 + lane) * 2;
    g_bf[base]            = h0;
    g_bf[base + 1]        = h1;
    g_bf[base + 1024]     = l0;
    g_bf[base + 1024 + 1] = l1;
}

// ---------------- 0b: A fragments (im2col + fp16 hi/lo, fragment-ordered) ----------------
// m16n8k16 A-frag (row-major 16x16): a0={(r,2c),(r,2c+1)}, a1={(r+8,2c),..},
// a2={(r,2c+8),..}, a3={(r+8,2c+8),..};  r = lane>>2, c = lane&3.
__global__ __launch_bounds__(256) void afrag_kernel(const float* __restrict__ x) {
    int id   = blockIdx.x * 256 + threadIdx.x;   // 128*96*8*32 = 3,145,728 exactly
    int lane = id & 31;
    int t    = (id >> 5) & 7;
    int rest = id >> 8;                          // mb*96 + ch
    int ch   = rest % CHUNKS;
    int mb   = rest / CHUNKS;
    int r  = lane >> 2;
    int m0 = mb * 128 + t * 16 + r;
    int b  = m0 >> 11, n = m0 & (SEQ - 1);
    int k0 = ch * 16 + (lane & 3) * 2;           // chunk never straddles a tap (512%16==0)
    int tap = k0 >> 9, d = k0 & 511;             // d, d+1, d+8, d+9 all in-tap
    int ra = n + tap - 1, rb = ra + 8;
    float2 p00 = make_float2(0.f, 0.f), p01 = p00, p10 = p00, p11 = p00;
    if ((unsigned)ra < SEQ) {
        const float* p = x + ((size_t)(b * SEQ + ra) * DIM + d);
        p00 = *reinterpret_cast<const float2*>(p);
        p01 = *reinterpret_cast<const float2*>(p + 8);
    }
    if ((unsigned)rb < SEQ) {
        const float* p = x + ((size_t)(b * SEQ + rb) * DIM + d);
        p10 = *reinterpret_cast<const float2*>(p);
        p11 = *reinterpret_cast<const float2*>(p + 8);
    }
    uint32_t hi[4], lo[4];
    split2(p00.x, p00.y, hi[0], lo[0]);   // a0: (r, 2c..2c+1)
    split2(p10.x, p10.y, hi[1], lo[1]);   // a1: (r+8, ..)
    split2(p01.x, p01.y, hi[2], lo[2]);   // a2: (r, 2c+8..)
    split2(p11.x, p11.y, hi[3], lo[3]);   // a3: (r+8, 2c+8..)
    size_t base = (size_t)rest * 2048 + (t * 32 + lane) * 4;
    *reinterpret_cast<uint4*>(g_af + base)        = *reinterpret_cast<uint4*>(hi);
    *reinterpret_cast<uint4*>(g_af + base + 1024) = *reinterpret_cast<uint4*>(lo);
}

// ---------------- 1: conv GEMM via mma.sync f16 x3-pass + bias + ReLU ----------------
// 256 thr = 8 warps (warpM 2 x warpN 4), warp tile 64x32; 3-stage cp.async pipeline.
// Stage 16KB: [A hi 4K | A lo 4K | B hi 4K | B lo 4K]; 48 MMA/warp/chunk.
__global__ __launch_bounds__(256) void conv_mma_kernel(const float* __restrict__ conv_b) {
    extern __shared__ float smem[];
    const uint32_t sb = smem_u32(smem);
    const int tid  = threadIdx.x;
    const int wid  = tid >> 5, lane = tid & 31;
    const int warpM = wid & 1, warpN = wid >> 1;
    const int mb = blockIdx.y, nb = blockIdx.x;
    const uint32_t* Ag = g_af + (size_t)mb * CHUNKS * 2048;
    const uint32_t* Bg = g_bf + (size_t)nb * CHUNKS * 2048;

    float acc[4][4][4];
#pragma unroll
    for (int i = 0; i < 4; i++)
#pragma unroll
        for (int j = 0; j < 4; j++)
#pragma unroll
            for (int q = 0; q < 4; q++) acc[i][j][q] = 0.f;

    auto issue = [&](int c) {
        uint32_t sA = sb + (uint32_t)(c % 3) * 16384u;
        const uint32_t* ga = Ag + (size_t)c * 2048;
        const uint32_t* gb = Bg + (size_t)c * 2048;
#pragma unroll
        for (int i = 0; i < 2; i++) cp16(sA + (i * 256 + tid) * 16, ga + (i * 256 + tid) * 4);
#pragma unroll
        for (int i = 0; i < 2; i++) cp16(sA + 8192 + (i * 256 + tid) * 16, gb + (i * 256 + tid) * 4);
        asm volatile("cp.async.commit_group;" ::: "memory");
    };

    issue(0);
    issue(1);

    for (int c = 0; c < CHUNKS; c++) {
        if (c < CHUNKS - 1)
            asm volatile("cp.async.wait_group 1;" ::: "memory");
        else
            asm volatile("cp.async.wait_group 0;" ::: "memory");
        __syncthreads();                    // chunk c visible; all warps done with c-1
        if (c + 2 < CHUNKS) issue(c + 2);   // stage (c+2)%3 == (c-1)%3, freed by the sync

        uint32_t Ab = sb + (uint32_t)(c % 3) * 16384u;
        uint32_t Bb = Ab + 8192;
        uint32_t ah[4][4], al[4][4], bh[4][2], bl[4][2];
#pragma unroll
        for (int tt = 0; tt < 4; tt++) {
            uint32_t a = Ab + (((warpM * 4 + tt) * 32 + lane) << 4);
            lds128(ah[tt], a);
            lds128(al[tt], a + 4096);
        }
#pragma unroll
        for (int uu = 0; uu < 4; uu++) {
            uint32_t a = Bb + (((warpN * 4 + uu) * 32 + lane) << 3);
            lds64(bh[uu], a);
            lds64(bl[uu], a + 4096);
        }
#pragma unroll
        for (int tt = 0; tt < 4; tt++)
#pragma unroll
            for (int uu = 0; uu < 4; uu++) {
                mma16(acc[tt][uu], ah[tt], bh[uu]);   // hi*hi
                mma16(acc[tt][uu], ah[tt], bl[uu]);   // hi*lo
                mma16(acc[tt][uu], al[tt], bh[uu]);   // lo*hi
            }
    }

    // epilogue: bias + ReLU -> g_h.  c-frag: c0=(r,2c), c1=(r,2c+1), c2=(r+8,2c), c3=(r+8,2c+1)
    const int row0 = mb * 128, col0 = nb * 128;
#pragma unroll
    for (int tt = 0; tt < 4; tt++) {
        int m0 = row0 + warpM * 64 + tt * 16 + (lane >> 2);
#pragma unroll
        for (int uu = 0; uu < 4; uu++) {
            int o0 = col0 + warpN * 32 + uu * 8 + 2 * (lane & 3);
            float2 bias = *reinterpret_cast<const float2*>(conv_b + o0);
            float2 v0, v1;
            v0.x = fmaxf(acc[tt][uu][0] + bias.x, 0.f);
            v0.y = fmaxf(acc[tt][uu][1] + bias.y, 0.f);
            v1.x = fmaxf(acc[tt][uu][2] + bias.x, 0.f);
            v1.y = fmaxf(acc[tt][uu][3] + bias.y, 0.f);
            *reinterpret_cast<float2*>(g_h + (size_t)m0 * HID + o0)       = v0;
            *reinterpret_cast<float2*>(g_h + (size_t)(m0 + 8) * HID + o0) = v1;
        }
    }
}

// ---------------- 2: LayerNorm + 2-col projection + argmax ----------------
__device__ __forceinline__ float block_reduce(float val, float* red, int t) {
#pragma unroll
    for (int off = 16; off; off >>= 1)
        val += __shfl_down_sync(0xffffffffu, val, off);
    int lane = t & 31, w = t >> 5;
    __syncthreads();
    if (lane == 0) red[w] = val;
    __syncthreads();
    float r = 0.f;
#pragma unroll
    for (int i = 0; i < 8; i++) r += red[i];
    return r;
}

__global__ __launch_bounds__(256) void ln_proj_kernel(const float* __restrict__ ln_g,
                                                      const float* __restrict__ ln_b,
                                                      const float* __restrict__ proj_w,
                                                      const float* __restrict__ proj_b,
                                                      float* __restrict__ out_probs) {
    const int m = blockIdx.x;
    const int t = threadIdx.x;
    const float* hrow = g_h + (size_t)m * HID;
    __shared__ float red[8];

    float v[4];
    float s = 0.f;
#pragma unroll
    for (int j = 0; j < 4; j++) { v[j] = hrow[t + j * 256]; s += v[j]; }

    float mu = block_reduce(s, red, t) * (1.f / HID);
    float sq = 0.f;
#pragma unroll
    for (int j = 0; j < 4; j++) { float d = v[j] - mu; sq += d * d; }
    float var = block_reduce(sq, red, t) * (1.f / HID);
    float rs  = rsqrtf(var + 1e-5f);

    float p0 = 0.f, p1 = 0.f;
#pragma unroll
    for (int j = 0; j < 4; j++) {
        int o = t + j * 256;
        float y = (v[j] - mu) * rs * ln_g[o] + ln_b[o];
        float2 w2 = *reinterpret_cast<const float2*>(proj_w + 2 * o);
        p0 += y * w2.x;
        p1 += y * w2.y;
    }
    p0 = block_reduce(p0, red, t);
    p1 = block_reduce(p1, red, t);
    if (t == 0) {
        p0 += proj_b[0];
        p1 += proj_b[1];
        out_probs[2 * m]     = p0;
        out_probs[2 * m + 1] = p1;
        g_flag[m] = (p1 > p0) ? 1 : 0;   // argmax: index 1 only if strictly greater
    }
}

// ---------------- 3: stable compaction of boundary positions ----------------
__global__ __launch_bounds__(1024) void compact_kernel() {
    const int b = blockIdx.x;
    const int t = threadIdx.x;
    __shared__ int buf[2][1024];

    const int n0 = 2 * t, n1 = 2 * t + 1;
    int k0 = (n0 == 0) ? 0 : ((n0 == SEQ - 1) ? 1 : (g_flag[b * SEQ + n0] == 0));
    int k1 = (n1 == SEQ - 1) ? 1 : (g_flag[b * SEQ + n1] == 0);
    int pairsum = k0 + k1;

    int src = 0;
    buf[0][t] = pairsum;
    __syncthreads();
    int incl = pairsum;
    for (int off = 1; off < 1024; off <<= 1) {
        incl = buf[src][t];
        if (t >= off) incl += buf[src][t - off];
        buf[1 - src][t] = incl;
        src ^= 1;
        __syncthreads();
    }
    int excl = incl - pairsum;

    g_groups[b * SEQ + n0] = 0;
    g_groups[b * SEQ + n1] = 0;
    __syncthreads();
    if (k0) g_groups[b * SEQ + excl]      = n0 + 1;
    if (k1) g_groups[b * SEQ + excl + k0] = n1 + 1;
}

// ---------------- 4: grouping matrix (interval indicator) ----------------
__global__ __launch_bounds__(256) void grouping_kernel(float* __restrict__ out) {
    unsigned e = blockIdx.x * 256u + threadIdx.x;
    int c = e & 511;
    int i = (e >> 9) & (SEQ - 1);
    int b = e >> 20;
    int Gi = g_groups[b * SEQ + i];
    int Gp = (i > 0) ? g_groups[b * SEQ + i - 1] : 0;
    int t0 = 4 * c + 1;
    float4 v;
    v.x = (t0     > Gp && t0     <= Gi) ? 1.f : 0.f;
    v.y = (t0 + 1 > Gp && t0 + 1 <= Gi) ? 1.f : 0.f;
    v.z = (t0 + 2 > Gp && t0 + 2 <= Gi) ? 1.f : 0.f;
    v.w = (t0 + 3 > Gp && t0 + 3 <= Gi) ? 1.f : 0.f;
    *reinterpret_cast<float4*>(out + ((size_t)(b * SEQ + i) * SEQ + 4 * c)) = v;
}

// ---------------- launch ----------------
extern "C" void kernel_launch(void* const* d_in, const int* in_sizes, int n_in,
                              void* d_out, int out_size) {
    const float* x      = (const float*)d_in[0];
    const float* conv_w = (const float*)d_in[1];
    const float* conv_b = (const float*)d_in[2];
    const float* ln_g   = (const float*)d_in[3];
    const float* ln_b   = (const float*)d_in[4];
    const float* proj_w = (const float*)d_in[5];
    const float* proj_b = (const float*)d_in[6];

    float* out       = (float*)d_out;
    float* out_probs = out;                          // (B,N,2)
    float* out_mat   = out + (size_t)M_TOT * 2;      // (B,N,N)

    bfrag_kernel<<<1536, 256>>>(conv_w);
    afrag_kernel<<<12288, 256>>>(x);

    cudaFuncSetAttribute(conv_mma_kernel, cudaFuncAttributeMaxDynamicSharedMemorySize, 3 * 16384);
    conv_mma_kernel<<<dim3(NBLK, MBLK), 256, 3 * 16384>>>(conv_b);

    ln_proj_kernel<<<M_TOT, 256>>>(ln_g, ln_b, proj_w, proj_b, out_probs);

    compact_kernel<<<BSZ, 1024>>>();

    grouping_kernel<<<(BSZ * SEQ * (SEQ / 4)) / 256, 256>>>(out_mat);
}

// round 14
// speedup vs baseline: 3.5115x; 1.0646x over previous
#include <cuda_runtime.h>
#include <cuda_fp16.h>
#include <cstdint>

#define BSZ 8
#define SEQ 2048
#define DIM 512
#define HID 1024
#define M_TOT (BSZ * SEQ)   /* 16384 */
#define K_TOT (3 * DIM)     /* 1536  */

#define CHUNKS 96           /* K_TOT / 16 */
#define NBLK   8            /* HID / 128  */
#define MBLK   128          /* M_TOT / 128 */

// ---------------- scratch (no allocations allowed) ----------------
__device__ uint32_t g_af[(size_t)MBLK * CHUNKS * 2048];  // 100 MB fp16 A frags [hi|lo]
__device__ uint32_t g_bf[(size_t)NBLK * CHUNKS * 2048];  // 6.3 MB fp16 B frags [hi|lo]
__device__ float g_part[(size_t)M_TOT * 32 * 4];         // 8 MB per-row partials (s1,s2,q0,q1) x 32 slices
__device__ float g_gw0[HID], g_gw1[HID];                 // ln_g * proj_w columns
__device__ float g_cst[4];                               // G0, G1, C0, C1
__device__ int   g_flag[M_TOT];
__device__ int   g_groups[BSZ * SEQ];

// ---------------- helpers ----------------
__device__ __forceinline__ uint32_t smem_u32(const void* p) {
    uint32_t a;
    asm("{ .reg .u64 t; cvta.to.shared.u64 t, %1; cvt.u32.u64 %0, t; }" : "=r"(a) : "l"(p));
    return a;
}
// fp16 two-way split: v = hi + lo (hi 11 bits, lo next 11 bits)
__device__ __forceinline__ void split2(float a, float b, uint32_t& hi, uint32_t& lo) {
    __half ha = __float2half_rn(a), hb = __float2half_rn(b);
    __half la = __float2half_rn(a - __half2float(ha));
    __half lb = __float2half_rn(b - __half2float(hb));
    __half2 h2 = __halves2half2(ha, hb), l2 = __halves2half2(la, lb);
    hi = *reinterpret_cast<uint32_t*>(&h2);
    lo = *reinterpret_cast<uint32_t*>(&l2);
}
__device__ __forceinline__ void cp16(uint32_t s, const void* g) {
    asm volatile("cp.async.cg.shared.global [%0], [%1], 16;" :: "r"(s), "l"(g) : "memory");
}
__device__ __forceinline__ void lds128(uint32_t* r, uint32_t a) {
    asm volatile("ld.shared.v4.b32 {%0,%1,%2,%3}, [%4];"
                 : "=r"(r[0]), "=r"(r[1]), "=r"(r[2]), "=r"(r[3]) : "r"(a));
}
__device__ __forceinline__ void lds64(uint32_t* r, uint32_t a) {
    asm volatile("ld.shared.v2.b32 {%0,%1}, [%2];" : "=r"(r[0]), "=r"(r[1]) : "r"(a));
}
__device__ __forceinline__ void mma16(float* c, const uint32_t* a, const uint32_t* b) {
    asm volatile(
        "mma.sync.aligned.m16n8k16.row.col.f32.f16.f16.f32 "
        "{%0,%1,%2,%3}, {%4,%5,%6,%7}, {%8,%9}, {%0,%1,%2,%3};"
        : "+f"(c[0]), "+f"(c[1]), "+f"(c[2]), "+f"(c[3])
        : "r"(a[0]), "r"(a[1]), "r"(a[2]), "r"(a[3]), "r"(b[0]), "r"(b[1]));
}

// ---------------- 0a: B fragments (weights, fp16 hi/lo) ----------------
__global__ void bfrag_kernel(const float* __restrict__ conv_w) {
    int id   = blockIdx.x * 256 + threadIdx.x;   // 393216 exactly
    int lane = id & 31;
    int u    = (id >> 5) & 15;
    int rest = id >> 9;                          // nb*96 + ch
    int ch   = rest % CHUNKS;
    int nb   = rest / CHUNKS;
    int o  = nb * 128 + u * 8 + (lane >> 2);
    int k0 = ch * 16 + (lane & 3) * 2;
    int tap = k0 >> 9, d = k0 & 511;
    const float* wp = conv_w + (size_t)o * K_TOT + tap;
    float w0 = wp[(d    ) * 3], w1 = wp[(d + 1) * 3];
    float w2 = wp[(d + 8) * 3], w3 = wp[(d + 9) * 3];
    uint32_t h0, l0, h1, l1;
    split2(w0, w1, h0, l0);
    split2(w2, w3, h1, l1);
    size_t base = (size_t)rest * 2048 + (u * 32 + lane) * 2;
    g_bf[base]            = h0;
    g_bf[base + 1]        = h1;
    g_bf[base + 1024]     = l0;
    g_bf[base + 1024 + 1] = l1;
}

// ---------------- 0b: A fragments (im2col + fp16 hi/lo, fragment-ordered) ----------------
__global__ __launch_bounds__(256) void afrag_kernel(const float* __restrict__ x) {
    int id   = blockIdx.x * 256 + threadIdx.x;   // 3,145,728 exactly
    int lane = id & 31;
    int t    = (id >> 5) & 7;
    int rest = id >> 8;                          // mb*96 + ch
    int ch   = rest % CHUNKS;
    int mb   = rest / CHUNKS;
    int r  = lane >> 2;
    int m0 = mb * 128 + t * 16 + r;
    int b  = m0 >> 11, n = m0 & (SEQ - 1);
    int k0 = ch * 16 + (lane & 3) * 2;
    int tap = k0 >> 9, d = k0 & 511;
    int ra = n + tap - 1, rb = ra + 8;
    float2 p00 = make_float2(0.f, 0.f), p01 = p00, p10 = p00, p11 = p00;
    if ((unsigned)ra < SEQ) {
        const float* p = x + ((size_t)(b * SEQ + ra) * DIM + d);
        p00 = *reinterpret_cast<const float2*>(p);
        p01 = *reinterpret_cast<const float2*>(p + 8);
    }
    if ((unsigned)rb < SEQ) {
        const float* p = x + ((size_t)(b * SEQ + rb) * DIM + d);
        p10 = *reinterpret_cast<const float2*>(p);
        p11 = *reinterpret_cast<const float2*>(p + 8);
    }
    uint32_t hi[4], lo[4];
    split2(p00.x, p00.y, hi[0], lo[0]);
    split2(p10.x, p10.y, hi[1], lo[1]);
    split2(p01.x, p01.y, hi[2], lo[2]);
    split2(p11.x, p11.y, hi[3], lo[3]);
    size_t base = (size_t)rest * 2048 + (t * 32 + lane) * 4;
    *reinterpret_cast<uint4*>(g_af + base)        = *reinterpret_cast<uint4*>(hi);
    *reinterpret_cast<uint4*>(g_af + base + 1024) = *reinterpret_cast<uint4*>(lo);
}

// ---------------- 0c: LN/proj constants ----------------
// gw_j[o] = ln_g[o]*proj_w[o][j];  G_j = sum gw_j;  C_j = sum ln_b[o]*proj_w[o][j] + proj_b[j]
__global__ void prep_kernel(const float* __restrict__ ln_g, const float* __restrict__ ln_b,
                            const float* __restrict__ proj_w, const float* __restrict__ proj_b) {
    int o = threadIdx.x;            // 1024 threads
    float2 w = *reinterpret_cast<const float2*>(proj_w + 2 * o);
    float g = ln_g[o], b = ln_b[o];
    float v0 = g * w.x, v1 = g * w.y;
    g_gw0[o] = v0;
    g_gw1[o] = v1;
    float c0 = b * w.x, c1 = b * w.y;
    __shared__ float red[32][4];
#pragma unroll
    for (int off = 16; off; off >>= 1) {
        v0 += __shfl_down_sync(~0u, v0, off);
        v1 += __shfl_down_sync(~0u, v1, off);
        c0 += __shfl_down_sync(~0u, c0, off);
        c1 += __shfl_down_sync(~0u, c1, off);
    }
    int lane = o & 31, w32 = o >> 5;
    if (lane == 0) { red[w32][0] = v0; red[w32][1] = v1; red[w32][2] = c0; red[w32][3] = c1; }
    __syncthreads();
    if (o == 0) {
        float a0 = 0, a1 = 0, a2 = 0, a3 = 0;
#pragma unroll
        for (int i = 0; i < 32; i++) { a0 += red[i][0]; a1 += red[i][1]; a2 += red[i][2]; a3 += red[i][3]; }
        g_cst[0] = a0;                 // G0
        g_cst[1] = a1;                 // G1
        g_cst[2] = a2 + proj_b[0];     // C0
        g_cst[3] = a3 + proj_b[1];     // C1
    }
}

// ---------------- 1: conv GEMM (f16 x3-pass) + fused LN/proj partial sums ----------------
// 8 warps (warpM 2 x warpN 4), warp tile 64x32; 3-stage cp.async pipeline.
// Epilogue: per-row partials (s1, s2, q0, q1) over this warp's 32 cols -> g_part[m][nb*4+warpN].
__global__ __launch_bounds__(256) void conv_mma_kernel(const float* __restrict__ conv_b) {
    extern __shared__ float smem[];
    const uint32_t sb = smem_u32(smem);
    const int tid  = threadIdx.x;
    const int wid  = tid >> 5, lane = tid & 31;
    const int warpM = wid & 1, warpN = wid >> 1;
    const int mb = blockIdx.y, nb = blockIdx.x;
    const uint32_t* Ag = g_af + (size_t)mb * CHUNKS * 2048;
    const uint32_t* Bg = g_bf + (size_t)nb * CHUNKS * 2048;

    float acc[4][4][4];
#pragma unroll
    for (int i = 0; i < 4; i++)
#pragma unroll
        for (int j = 0; j < 4; j++)
#pragma unroll
            for (int q = 0; q < 4; q++) acc[i][j][q] = 0.f;

    auto issue = [&](int c) {
        uint32_t sA = sb + (uint32_t)(c % 3) * 16384u;
        const uint32_t* ga = Ag + (size_t)c * 2048;
        const uint32_t* gb = Bg + (size_t)c * 2048;
#pragma unroll
        for (int i = 0; i < 2; i++) cp16(sA + (i * 256 + tid) * 16, ga + (i * 256 + tid) * 4);
#pragma unroll
        for (int i = 0; i < 2; i++) cp16(sA + 8192 + (i * 256 + tid) * 16, gb + (i * 256 + tid) * 4);
        asm volatile("cp.async.commit_group;" ::: "memory");
    };

    issue(0);
    issue(1);

    for (int c = 0; c < CHUNKS; c++) {
        if (c < CHUNKS - 1)
            asm volatile("cp.async.wait_group 1;" ::: "memory");
        else
            asm volatile("cp.async.wait_group 0;" ::: "memory");
        __syncthreads();
        if (c + 2 < CHUNKS) issue(c + 2);

        uint32_t Ab = sb + (uint32_t)(c % 3) * 16384u;
        uint32_t Bb = Ab + 8192;
        uint32_t ah[4][4], al[4][4], bh[4][2], bl[4][2];
#pragma unroll
        for (int tt = 0; tt < 4; tt++) {
            uint32_t a = Ab + (((warpM * 4 + tt) * 32 + lane) << 4);
            lds128(ah[tt], a);
            lds128(al[tt], a + 4096);
        }
#pragma unroll
        for (int uu = 0; uu < 4; uu++) {
            uint32_t a = Bb + (((warpN * 4 + uu) * 32 + lane) << 3);
            lds64(bh[uu], a);
            lds64(bl[uu], a + 4096);
        }
#pragma unroll
        for (int tt = 0; tt < 4; tt++)
#pragma unroll
            for (int uu = 0; uu < 4; uu++) {
                mma16(acc[tt][uu], ah[tt], bh[uu]);   // hi*hi
                mma16(acc[tt][uu], ah[tt], bl[uu]);   // hi*lo
                mma16(acc[tt][uu], al[tt], bh[uu]);   // lo*hi
            }
    }

    // ---- fused epilogue: ReLU(acc+bias) -> per-row partials over this warp's 32 cols
    const int col0 = nb * 128;
    const int row0 = mb * 128;
    const int r = lane >> 2;
    const int slice = nb * 4 + warpN;
#pragma unroll
    for (int tt = 0; tt < 4; tt++) {
        float p0[4] = {0, 0, 0, 0}, p1[4] = {0, 0, 0, 0};   // rows tt*16+r, tt*16+8+r
#pragma unroll
        for (int uu = 0; uu < 4; uu++) {
            int o0 = col0 + warpN * 32 + uu * 8 + 2 * (lane & 3);
            float2 bias = *reinterpret_cast<const float2*>(conv_b + o0);
            float2 w0v  = *reinterpret_cast<const float2*>(g_gw0 + o0);
            float2 w1v  = *reinterpret_cast<const float2*>(g_gw1 + o0);
            float h00 = fmaxf(acc[tt][uu][0] + bias.x, 0.f);
            float h01 = fmaxf(acc[tt][uu][1] + bias.y, 0.f);
            float h10 = fmaxf(acc[tt][uu][2] + bias.x, 0.f);
            float h11 = fmaxf(acc[tt][uu][3] + bias.y, 0.f);
            p0[0] += h00 + h01;
            p0[1] += h00 * h00 + h01 * h01;
            p0[2] += h00 * w0v.x + h01 * w0v.y;
            p0[3] += h00 * w1v.x + h01 * w1v.y;
            p1[0] += h10 + h11;
            p1[1] += h10 * h10 + h11 * h11;
            p1[2] += h10 * w0v.x + h11 * w0v.y;
            p1[3] += h10 * w1v.x + h11 * w1v.y;
        }
#pragma unroll
        for (int q = 0; q < 4; q++) {
            p0[q] += __shfl_xor_sync(~0u, p0[q], 1);
            p0[q] += __shfl_xor_sync(~0u, p0[q], 2);
            p1[q] += __shfl_xor_sync(~0u, p1[q], 1);
            p1[q] += __shfl_xor_sync(~0u, p1[q], 2);
        }
        if ((lane & 3) == 0) {
            int m0 = row0 + warpM * 64 + tt * 16 + r;
            *reinterpret_cast<float4*>(g_part + ((size_t)m0 * 32 + slice) * 4) =
                make_float4(p0[0], p0[1], p0[2], p0[3]);
            *reinterpret_cast<float4*>(g_part + ((size_t)(m0 + 8) * 32 + slice) * 4) =
                make_float4(p1[0], p1[1], p1[2], p1[3]);
        }
    }
}

// ---------------- 2: finish probs + argmax (one warp per row) ----------------
__global__ __launch_bounds__(256) void probs_kernel(float* __restrict__ out_probs) {
    int gid  = blockIdx.x * 256 + threadIdx.x;
    int m    = gid >> 5;
    int lane = gid & 31;
    float4 v = *reinterpret_cast<const float4*>(g_part + ((size_t)m * 32 + lane) * 4);
#pragma unroll
    for (int off = 16; off; off >>= 1) {
        v.x += __shfl_down_sync(~0u, v.x, off);
        v.y += __shfl_down_sync(~0u, v.y, off);
        v.z += __shfl_down_sync(~0u, v.z, off);
        v.w += __shfl_down_sync(~0u, v.w, off);
    }
    if (lane == 0) {
        float mu  = v.x * (1.f / HID);
        float var = v.y * (1.f / HID) - mu * mu;
        float rs  = rsqrtf(var + 1e-5f);
        float p0 = rs * (v.z - mu * g_cst[0]) + g_cst[2];
        float p1 = rs * (v.w - mu * g_cst[1]) + g_cst[3];
        out_probs[2 * m]     = p0;
        out_probs[2 * m + 1] = p1;
        g_flag[m] = (p1 > p0) ? 1 : 0;   // argmax: index 1 only if strictly greater
    }
}

// ---------------- 3: stable compaction of boundary positions ----------------
__global__ __launch_bounds__(1024) void compact_kernel() {
    const int b = blockIdx.x;
    const int t = threadIdx.x;
    __shared__ int buf[2][1024];

    const int n0 = 2 * t, n1 = 2 * t + 1;
    int k0 = (n0 == 0) ? 0 : ((n0 == SEQ - 1) ? 1 : (g_flag[b * SEQ + n0] == 0));
    int k1 = (n1 == SEQ - 1) ? 1 : (g_flag[b * SEQ + n1] == 0);
    int pairsum = k0 + k1;

    int src = 0;
    buf[0][t] = pairsum;
    __syncthreads();
    int incl = pairsum;
    for (int off = 1; off < 1024; off <<= 1) {
        incl = buf[src][t];
        if (t >= off) incl += buf[src][t - off];
        buf[1 - src][t] = incl;
        src ^= 1;
        __syncthreads();
    }
    int excl = incl - pairsum;

    g_groups[b * SEQ + n0] = 0;
    g_groups[b * SEQ + n1] = 0;
    __syncthreads();
    if (k0) g_groups[b * SEQ + excl]      = n0 + 1;
    if (k1) g_groups[b * SEQ + excl + k0] = n1 + 1;
}

// ---------------- 4: grouping matrix (interval indicator) ----------------
__global__ __launch_bounds__(256) void grouping_kernel(float* __restrict__ out) {
    unsigned e = blockIdx.x * 256u + threadIdx.x;
    int c = e & 511;
    int i = (e >> 9) & (SEQ - 1);
    int b = e >> 20;
    int Gi = g_groups[b * SEQ + i];
    int Gp = (i > 0) ? g_groups[b * SEQ + i - 1] : 0;
    int t0 = 4 * c + 1;
    float4 v;
    v.x = (t0     > Gp && t0     <= Gi) ? 1.f : 0.f;
    v.y = (t0 + 1 > Gp && t0 + 1 <= Gi) ? 1.f : 0.f;
    v.z = (t0 + 2 > Gp && t0 + 2 <= Gi) ? 1.f : 0.f;
    v.w = (t0 + 3 > Gp && t0 + 3 <= Gi) ? 1.f : 0.f;
    *reinterpret_cast<float4*>(out + ((size_t)(b * SEQ + i) * SEQ + 4 * c)) = v;
}

// ---------------- launch ----------------
extern "C" void kernel_launch(void* const* d_in, const int* in_sizes, int n_in,
                              void* d_out, int out_size) {
    const float* x      = (const float*)d_in[0];
    const float* conv_w = (const float*)d_in[1];
    const float* conv_b = (const float*)d_in[2];
    const float* ln_g   = (const float*)d_in[3];
    const float* ln_b   = (const float*)d_in[4];
    const float* proj_w = (const float*)d_in[5];
    const float* proj_b = (const float*)d_in[6];

    float* out       = (float*)d_out;
    float* out_probs = out;                          // (B,N,2)
    float* out_mat   = out + (size_t)M_TOT * 2;      // (B,N,N)

    bfrag_kernel<<<1536, 256>>>(conv_w);
    afrag_kernel<<<12288, 256>>>(x);
    prep_kernel<<<1, 1024>>>(ln_g, ln_b, proj_w, proj_b);

    cudaFuncSetAttribute(conv_mma_kernel, cudaFuncAttributeMaxDynamicSharedMemorySize, 3 * 16384);
    conv_mma_kernel<<<dim3(NBLK, MBLK), 256, 3 * 16384>>>(conv_b);

    probs_kernel<<<M_TOT / 8, 256>>>(out_probs);

    compact_kernel<<<BSZ, 1024>>>();

    grouping_kernel<<<(BSZ * SEQ * (SEQ / 4)) / 256, 256>>>(out_mat);
}